// round 2
// baseline (speedup 1.0000x reference)
#include <cuda_runtime.h>
#include <cuda_bf16.h>
#include <math.h>

// Problem constants
#define BB 8
#define NN 256
#define FF 256
#define HH 128
#define TT 256
#define G4 512           // 4*H gates
#define ROWS (BB*NN)     // 2048

// ---------------- scratch (device globals; no allocation allowed) ----------------
__device__ float g_S[BB*FF];                 // column sums
__device__ float g_pk1[BB*NN*FF];            // P @ x
__device__ float g_ctmp[BB*NN*FF];           // cheb pre-LN
__device__ float g_cout[BB*NN*FF];           // cheb out (layer1 input)
__device__ float g_gin[2*ROWS*G4];           // per-dir input gates [d][B*T][512]
__device__ float g_h1[BB*NN*2*HH];           // layer1 concat output
__device__ float g_h2[BB*NN*2*HH];           // layer2 concat output
__device__ float g_wt[2*2*G4*HH];            // transposed Whh: [l][d][k4][j][4]

// ---------------- small helpers ----------------
__device__ __forceinline__ float blocksum256(float v, volatile float* red) {
    #pragma unroll
    for (int o = 16; o; o >>= 1) v += __shfl_xor_sync(0xffffffffu, v, o);
    if ((threadIdx.x & 31) == 0) red[threadIdx.x >> 5] = v;
    __syncthreads();
    float s = 0.f;
    #pragma unroll
    for (int i = 0; i < 8; i++) s += red[i];
    return s;
}

// ---------------- trivial kernels ----------------
__global__ void fill_tg_kernel(float* __restrict__ tg) {
    int i = blockIdx.x * blockDim.x + threadIdx.x;
    if (i < BB*NN*NN) tg[i] = 1.0f / 256.0f;   // exact: softmax of constant rows
}

__global__ void colsum_kernel(const float* __restrict__ x, float* __restrict__ S) {
    int b = blockIdx.x, f = threadIdx.x;
    float s = 0.f;
    const float* xb = x + (size_t)b * NN * FF + f;
    #pragma unroll 4
    for (int n = 0; n < NN; n++) s += xb[(size_t)n * FF];
    S[b * FF + f] = s;
}

__global__ void pk1_kernel(const float* __restrict__ x, const float* __restrict__ S,
                           float* __restrict__ p) {
    int i = blockIdx.x * blockDim.x + threadIdx.x;
    if (i >= BB*NN*FF) return;
    int b = i >> 16;          // / (NN*FF)
    int f = i & (FF - 1);
    p[i] = 0.5f * (x[i] + (1.0f / 256.0f) * S[b * FF + f]);
}

// transpose Whh[l][d][j][k] -> wt[l][d][k4][j][c]  (c = k%4), so a warp's
// float4 loads at fixed k4 across j are fully coalesced.
__global__ void prep_wt_kernel(const float* __restrict__ whh, float* __restrict__ wt) {
    int idx = blockIdx.x * blockDim.x + threadIdx.x;
    if (idx >= 4 * G4 * HH) return;
    int ld   = idx / (G4 * HH);
    int rem  = idx - ld * (G4 * HH);
    int k4   = rem / (G4 * 4);
    int rem2 = rem - k4 * (G4 * 4);
    int j    = rem2 >> 2;
    int c    = rem2 & 3;
    wt[idx] = whh[(size_t)(ld * G4 + j) * HH + 4 * k4 + c];
}

// ---------------- generic fp32 GEMM: C[M,N] = A[M,K] @ B (+beta*C + biases) ----
// BT=false: B is [K,N] row-major.  BT=true: B is [N,K] row-major (C=A@B^T).
template<bool BT, bool BETA>
__global__ __launch_bounds__(256)
void gemm64_kernel(const float* __restrict__ A, const float* __restrict__ B,
                   float* __restrict__ C, int M, int N, int K,
                   const float* __restrict__ bias0, const float* __restrict__ bias1)
{
    const int BM = 64, BN = 64, BK = 16;
    __shared__ float As[BK][BM];
    __shared__ float Bs[BK][BN];
    int tid = threadIdx.x;
    int tx = tid & 15, ty = tid >> 4;
    int bm = blockIdx.y * BM, bn = blockIdx.x * BN;

    float acc[4][4] = {};
    for (int k0 = 0; k0 < K; k0 += BK) {
        {   // A tile: 64 rows x 16 k, one float4 per thread
            int r = tid >> 2, kq = (tid & 3) * 4;
            float4 a = *(const float4*)(A + (size_t)(bm + r) * K + k0 + kq);
            As[kq + 0][r] = a.x; As[kq + 1][r] = a.y;
            As[kq + 2][r] = a.z; As[kq + 3][r] = a.w;
        }
        if (BT) {
            int r = tid >> 2, kq = (tid & 3) * 4;
            float4 bv = *(const float4*)(B + (size_t)(bn + r) * K + k0 + kq);
            Bs[kq + 0][r] = bv.x; Bs[kq + 1][r] = bv.y;
            Bs[kq + 2][r] = bv.z; Bs[kq + 3][r] = bv.w;
        } else {
            int kr = tid >> 4, cq = (tid & 15) * 4;
            float4 bv = *(const float4*)(B + (size_t)(k0 + kr) * N + bn + cq);
            *(float4*)&Bs[kr][cq] = bv;
        }
        __syncthreads();
        #pragma unroll
        for (int k = 0; k < BK; k++) {
            float ar[4], br[4];
            #pragma unroll
            for (int i = 0; i < 4; i++) ar[i] = As[k][ty * 4 + i];
            #pragma unroll
            for (int j = 0; j < 4; j++) br[j] = Bs[k][tx * 4 + j];
            #pragma unroll
            for (int i = 0; i < 4; i++)
                #pragma unroll
                for (int j = 0; j < 4; j++)
                    acc[i][j] = fmaf(ar[i], br[j], acc[i][j]);
        }
        __syncthreads();
    }
    #pragma unroll
    for (int i = 0; i < 4; i++) {
        int row = bm + ty * 4 + i;
        #pragma unroll
        for (int j = 0; j < 4; j++) {
            int col = bn + tx * 4 + j;
            float v = acc[i][j];
            if (BETA) v += C[(size_t)row * N + col];
            if (bias0) v += bias0[col];
            if (bias1) v += bias1[col];
            C[(size_t)row * N + col] = v;
        }
    }
}

// ---------------- LayerNorm over 256 elems per row ----------------
__global__ __launch_bounds__(256)
void ln256_kernel(const float* __restrict__ x, const float* __restrict__ g,
                  const float* __restrict__ bt, float* __restrict__ y)
{
    __shared__ float red1[8];
    __shared__ float red2[8];
    size_t row = blockIdx.x;
    float v = x[row * 256 + threadIdx.x];
    float m = blocksum256(v, red1) * (1.0f / 256.0f);
    float d = v - m;
    float var = blocksum256(d * d, red2) * (1.0f / 256.0f);
    float r = rsqrtf(var + 1e-5f);
    y[row * 256 + threadIdx.x] = d * r * g[threadIdx.x] + bt[threadIdx.x];
}

// ---------------- LSTM recurrent scan: one block per (batch, dir) -------------
// gin: [2][B][T][512] precomputed x@Wih^T + bih + bhh for this layer
// wt:  [2][32][512][4] transposed Whh for this layer
// hout:[B][T][256], dir d writes columns [d*128, d*128+128)
__global__ __launch_bounds__(512)
void lstm_scan_kernel(const float* __restrict__ gin, const float* __restrict__ wt,
                      float* __restrict__ hout)
{
    int b = blockIdx.x >> 1, d = blockIdx.x & 1;
    int tid = threadIdx.x;              // 0..511 = gate index
    __shared__ __align__(16) float hsh[HH];
    __shared__ float gsh[G4];

    const float4* W4 = ((const float4*)wt) + (size_t)d * 32 * G4;   // [k4][j]
    const float*  gb = gin + ((size_t)d * BB + b) * TT * G4;

    float c = 0.f;
    if (tid < HH) hsh[tid] = 0.f;
    __syncthreads();

    for (int s = 0; s < TT; s++) {
        int t = d ? (TT - 1 - s) : s;
        float p0 = gb[(size_t)t * G4 + tid];
        float p1 = 0.f, p2 = 0.f, p3 = 0.f;
        const float4* h4 = (const float4*)hsh;
        #pragma unroll
        for (int k4 = 0; k4 < 32; k4 += 4) {
            float4 w0 = W4[(size_t)(k4 + 0) * G4 + tid];
            float4 w1 = W4[(size_t)(k4 + 1) * G4 + tid];
            float4 w2 = W4[(size_t)(k4 + 2) * G4 + tid];
            float4 w3 = W4[(size_t)(k4 + 3) * G4 + tid];
            float4 h0 = h4[k4 + 0], h1v = h4[k4 + 1];
            float4 h2v = h4[k4 + 2], h3v = h4[k4 + 3];
            p0 = fmaf(w0.x, h0.x, fmaf(w0.y, h0.y, fmaf(w0.z, h0.z, fmaf(w0.w, h0.w, p0))));
            p1 = fmaf(w1.x, h1v.x, fmaf(w1.y, h1v.y, fmaf(w1.z, h1v.z, fmaf(w1.w, h1v.w, p1))));
            p2 = fmaf(w2.x, h2v.x, fmaf(w2.y, h2v.y, fmaf(w2.z, h2v.z, fmaf(w2.w, h2v.w, p2))));
            p3 = fmaf(w3.x, h3v.x, fmaf(w3.y, h3v.y, fmaf(w3.z, h3v.z, fmaf(w3.w, h3v.w, p3))));
        }
        gsh[tid] = (p0 + p1) + (p2 + p3);
        __syncthreads();                 // all reads of hsh done; gates ready
        if (tid < HH) {
            float ig = 1.0f / (1.0f + expf(-gsh[tid]));
            float fg = 1.0f / (1.0f + expf(-gsh[tid + 128]));
            float gg = tanhf(gsh[tid + 256]);
            float og = 1.0f / (1.0f + expf(-gsh[tid + 384]));
            c = fg * c + ig * gg;
            float h = og * tanhf(c);
            hsh[tid] = h;
            hout[((size_t)b * TT + t) * 256 + d * HH + tid] = h;
        }
        __syncthreads();                 // new h visible to all
    }
}

// ---------------- mean over nodes ----------------
__global__ void agg_kernel(const float* __restrict__ lo, float* __restrict__ agg) {
    int b = blockIdx.x, o = threadIdx.x;
    float s = 0.f;
    const float* lb = lo + (size_t)b * TT * 256 + o;
    #pragma unroll 4
    for (int t = 0; t < TT; t++) s += lb[(size_t)t * 256];
    agg[b * 256 + o] = s * (1.0f / 256.0f);
}

// ---------------- host launcher ----------------
extern "C" void kernel_launch(void* const* d_in, const int* in_sizes, int n_in,
                              void* d_out, int out_size)
{
    const float* x         = (const float*)d_in[0];
    const float* cheb_w    = (const float*)d_in[5];   // [2,256,256]
    const float* cheb_b    = (const float*)d_in[6];
    const float* ln_cheb_g = (const float*)d_in[7];
    const float* ln_cheb_b = (const float*)d_in[8];
    const float* w_ih      = (const float*)d_in[9];   // [2,2,512,256]
    const float* w_hh      = (const float*)d_in[10];  // [2,2,512,128]
    const float* b_ih      = (const float*)d_in[11];  // [2,2,512]
    const float* b_hh      = (const float*)d_in[12];
    const float* ln_out_g  = (const float*)d_in[13];
    const float* ln_out_b  = (const float*)d_in[14];

    float* out = (float*)d_out;
    float* agg = out;                          // [8,256]
    float* tg  = out + BB * 256;               // [8,256,256]
    float* lo  = tg + BB * NN * NN;            // [8,256,256]

    float *S, *pk1, *ctmp, *cout, *gin, *h1, *h2, *wt;
    cudaGetSymbolAddress((void**)&S,    g_S);
    cudaGetSymbolAddress((void**)&pk1,  g_pk1);
    cudaGetSymbolAddress((void**)&ctmp, g_ctmp);
    cudaGetSymbolAddress((void**)&cout, g_cout);
    cudaGetSymbolAddress((void**)&gin,  g_gin);
    cudaGetSymbolAddress((void**)&h1,   g_h1);
    cudaGetSymbolAddress((void**)&h2,   g_h2);
    cudaGetSymbolAddress((void**)&wt,   g_wt);

    // TG output: exact constant (LayerNorm(1) degenerates; softmax of const rows)
    fill_tg_kernel<<<2048, 256>>>(tg);

    // ChebConv: out = x@W0 + ((x + S/256)/2)@W1 + cheb_b, then LN
    colsum_kernel<<<BB, FF>>>(x, S);
    pk1_kernel<<<1024, 512>>>(x, S, pk1);
    gemm64_kernel<false, false><<<dim3(FF/64, ROWS/64), 256>>>(
        x, cheb_w, ctmp, ROWS, FF, FF, nullptr, nullptr);
    gemm64_kernel<false, true><<<dim3(FF/64, ROWS/64), 256>>>(
        pk1, cheb_w + FF * FF, ctmp, ROWS, FF, FF, cheb_b, nullptr);
    ln256_kernel<<<ROWS, 256>>>(ctmp, ln_cheb_g, ln_cheb_b, cout);

    // Whh transpose (coalesced layout for the scan)
    prep_wt_kernel<<<1024, 256>>>(w_hh, wt);

    // Layer 1: input gates (both dirs), then scan
    for (int d = 0; d < 2; d++) {
        gemm64_kernel<true, false><<<dim3(G4/64, ROWS/64), 256>>>(
            cout, w_ih + (size_t)d * G4 * FF, gin + (size_t)d * ROWS * G4,
            ROWS, G4, FF, b_ih + d * G4, b_hh + d * G4);
    }
    lstm_scan_kernel<<<16, 512>>>(gin, wt, h1);

    // Layer 2: input gates from concat(h1_fwd, h1_bwd), then scan
    for (int d = 0; d < 2; d++) {
        gemm64_kernel<true, false><<<dim3(G4/64, ROWS/64), 256>>>(
            h1, w_ih + (size_t)(2 + d) * G4 * FF, gin + (size_t)d * ROWS * G4,
            ROWS, G4, 2 * HH, b_ih + (2 + d) * G4, b_hh + (2 + d) * G4);
    }
    lstm_scan_kernel<<<16, 512>>>(gin, wt + 2 * G4 * HH, h2);

    // Final LN -> lstm_out, then node-mean -> agg
    ln256_kernel<<<ROWS, 256>>>(h2, ln_out_g, ln_out_b, lo);
    agg_kernel<<<BB, 256>>>(lo, agg);
}

// round 5
// speedup vs baseline: 1.5930x; 1.5930x over previous
#include <cuda_runtime.h>
#include <cuda_bf16.h>
#include <cstdint>
#include <math.h>

// Problem constants
#define BB 8
#define NN 256
#define FF 256
#define HH 128
#define TT 256
#define G4 512           // 4*H gates
#define ROWS (BB*NN)     // 2048

// ---------------- scratch (device globals; no allocation allowed) ----------------
__device__ float g_S[BB*FF];                 // column sums
__device__ float g_pk1[BB*NN*FF];            // P @ x
__device__ float g_ctmp[BB*NN*FF];           // cheb pre-LN
__device__ float g_cout[BB*NN*FF];           // cheb out (layer1 input)
__device__ float g_gin[ROWS*1024];           // input gates, both dirs: [B*T][1024]
__device__ float g_h1[BB*NN*2*HH];           // layer1 concat output
__device__ float g_h2[BB*NN*2*HH];           // layer2 concat output

// ---------------- small helpers ----------------
__device__ __forceinline__ float blocksum256(float v, volatile float* red) {
    #pragma unroll
    for (int o = 16; o; o >>= 1) v += __shfl_xor_sync(0xffffffffu, v, o);
    if ((threadIdx.x & 31) == 0) red[threadIdx.x >> 5] = v;
    __syncthreads();
    float s = 0.f;
    #pragma unroll
    for (int i = 0; i < 8; i++) s += red[i];
    return s;
}

__device__ __forceinline__ unsigned smem_u32(const void* p) {
    unsigned a;
    asm("{ .reg .u64 t; cvta.to.shared.u64 t, %1; cvt.u32.u64 %0, t; }"
        : "=r"(a) : "l"(p));
    return a;
}

__device__ __forceinline__ float sigmoidf_(float x) {
    return 1.0f / (1.0f + expf(-x));
}

// ---------------- trivial kernels ----------------
__global__ void fill_tg_kernel(float* __restrict__ tg) {
    int i = blockIdx.x * blockDim.x + threadIdx.x;
    if (i < BB*NN*NN) tg[i] = 1.0f / 256.0f;   // exact: softmax of constant rows
}

__global__ void colsum_kernel(const float* __restrict__ x, float* __restrict__ S) {
    int b = blockIdx.x, f = threadIdx.x;
    float s = 0.f;
    const float* xb = x + (size_t)b * NN * FF + f;
    #pragma unroll 4
    for (int n = 0; n < NN; n++) s += xb[(size_t)n * FF];
    S[b * FF + f] = s;
}

__global__ void pk1_kernel(const float* __restrict__ x, const float* __restrict__ S,
                           float* __restrict__ p) {
    int i = blockIdx.x * blockDim.x + threadIdx.x;
    if (i >= BB*NN*FF) return;
    int b = i >> 16;
    int f = i & (FF - 1);
    p[i] = 0.5f * (x[i] + (1.0f / 256.0f) * S[b * FF + f]);
}

// ---------------- generic fp32 GEMM: C[M,N] = A[M,K] @ B (+beta*C + biases) ----
// BT=false: B is [K,N] row-major.  BT=true: B is [N,K] row-major (C=A@B^T).
template<bool BT, bool BETA>
__global__ __launch_bounds__(256)
void gemm64_kernel(const float* __restrict__ A, const float* __restrict__ B,
                   float* __restrict__ C, int M, int N, int K,
                   const float* __restrict__ bias0, const float* __restrict__ bias1)
{
    const int BM = 64, BN = 64, BK = 16;
    __shared__ float As[BK][BM];
    __shared__ float Bs[BK][BN];
    int tid = threadIdx.x;
    int tx = tid & 15, ty = tid >> 4;
    int bm = blockIdx.y * BM, bn = blockIdx.x * BN;

    float acc[4][4] = {};
    for (int k0 = 0; k0 < K; k0 += BK) {
        {
            int r = tid >> 2, kq = (tid & 3) * 4;
            float4 a = *(const float4*)(A + (size_t)(bm + r) * K + k0 + kq);
            As[kq + 0][r] = a.x; As[kq + 1][r] = a.y;
            As[kq + 2][r] = a.z; As[kq + 3][r] = a.w;
        }
        if (BT) {
            int r = tid >> 2, kq = (tid & 3) * 4;
            float4 bv = *(const float4*)(B + (size_t)(bn + r) * K + k0 + kq);
            Bs[kq + 0][r] = bv.x; Bs[kq + 1][r] = bv.y;
            Bs[kq + 2][r] = bv.z; Bs[kq + 3][r] = bv.w;
        } else {
            int kr = tid >> 4, cq = (tid & 15) * 4;
            float4 bv = *(const float4*)(B + (size_t)(k0 + kr) * N + bn + cq);
            *(float4*)&Bs[kr][cq] = bv;
        }
        __syncthreads();
        #pragma unroll
        for (int k = 0; k < BK; k++) {
            float ar[4], br[4];
            #pragma unroll
            for (int i = 0; i < 4; i++) ar[i] = As[k][ty * 4 + i];
            #pragma unroll
            for (int j = 0; j < 4; j++) br[j] = Bs[k][tx * 4 + j];
            #pragma unroll
            for (int i = 0; i < 4; i++)
                #pragma unroll
                for (int j = 0; j < 4; j++)
                    acc[i][j] = fmaf(ar[i], br[j], acc[i][j]);
        }
        __syncthreads();
    }
    #pragma unroll
    for (int i = 0; i < 4; i++) {
        int row = bm + ty * 4 + i;
        #pragma unroll
        for (int j = 0; j < 4; j++) {
            int col = bn + tx * 4 + j;
            float v = acc[i][j];
            if (BETA) v += C[(size_t)row * N + col];
            if (bias0) v += bias0[col];
            if (bias1) v += bias1[col];
            C[(size_t)row * N + col] = v;
        }
    }
}

// ---------------- LayerNorm over 256 elems per row ----------------
__global__ __launch_bounds__(256)
void ln256_kernel(const float* __restrict__ x, const float* __restrict__ g,
                  const float* __restrict__ bt, float* __restrict__ y)
{
    __shared__ float red1[8];
    __shared__ float red2[8];
    size_t row = blockIdx.x;
    float v = x[row * 256 + threadIdx.x];
    float m = blocksum256(v, red1) * (1.0f / 256.0f);
    float d = v - m;
    float var = blocksum256(d * d, red2) * (1.0f / 256.0f);
    float r = rsqrtf(var + 1e-5f);
    y[row * 256 + threadIdx.x] = d * r * g[threadIdx.x] + bt[threadIdx.x];
}

// ---------------- LSTM scan: register-resident Whh, 4-CTA clusters ----------------
// One cluster of 4 CTAs per (batch, dir). CTA rank r owns gates [r*128, r*128+128).
// Thread tid owns gate (r*128+tid): its 128 Whh weights live in registers as f32x2.
// Per step: dot(W_row, h) via fma.rn.f32x2 -> all-to-all DSMEM gate broadcast ->
// cluster.sync -> each CTA redundantly computes identical (c, h) locally.
// gin: [B*T][1024] (col = d*512 + gate), whh: [2 dirs][512][128] for this layer.
__global__ void __launch_bounds__(128, 1) __cluster_dims__(4, 1, 1)
lstm_scan_cluster(const float* __restrict__ gin, const float* __restrict__ whh,
                  float* __restrict__ hout)
{
    __shared__ __align__(16) float hsh[HH];
    __shared__ __align__(16) float gb[2][G4];

    int tid = threadIdx.x;
    unsigned rank;
    asm("mov.u32 %0, %%cluster_ctarank;" : "=r"(rank));
    int pair = blockIdx.x >> 2;
    int b = pair >> 1, d = pair & 1;
    int gate = (int)rank * 128 + tid;

    // ---- load this thread's Whh row into registers (64 f32x2 pairs) ----
    unsigned long long w[64];
    const float2* wrow = (const float2*)(whh + ((size_t)d * G4 + gate) * HH);
    #pragma unroll
    for (int i = 0; i < 64; i++) {
        float2 t2 = wrow[i];
        asm("mov.b64 %0, {%1, %2};" : "=l"(w[i]) : "f"(t2.x), "f"(t2.y));
    }

    const float* gp = gin + ((size_t)b * TT) * 1024 + d * 512 + gate;

    hsh[tid] = 0.f;

    unsigned hadr = smem_u32(hsh);
    // DSMEM addresses of gb[par][gate] in each peer CTA
    unsigned gadr[2][4];
    #pragma unroll
    for (int par = 0; par < 2; par++) {
        unsigned la = smem_u32(&gb[par][gate]);
        #pragma unroll
        for (int peer = 0; peer < 4; peer++) {
            asm("mapa.shared::cluster.u32 %0, %1, %2;"
                : "=r"(gadr[par][peer]) : "r"(la), "r"(peer));
        }
    }

    // full cluster barrier: hsh init visible, peers launched
    asm volatile("barrier.cluster.arrive.aligned;" ::: "memory");
    asm volatile("barrier.cluster.wait.aligned;" ::: "memory");

    float c = 0.f;
    int t = d ? (TT - 1) : 0;
    const int tstep = d ? -1 : 1;
    float gcur = gp[(size_t)t * 1024];

    for (int s = 0; s < TT; s++) {
        // ---- dot(W_row, h) with packed f32x2 FMAs, 4 independent chains ----
        // NOTE: loads MUST be asm volatile — hsh changes every iteration; a
        // non-volatile asm is "pure" to NVVM and gets hoisted out of the loop.
        unsigned long long a0 = 0ull, a1 = 0ull, a2 = 0ull, a3 = 0ull;
        #pragma unroll
        for (int i = 0; i < 64; i += 4) {
            unsigned long long h0, h1, h2, h3;
            asm volatile("ld.shared.b64 %0, [%1];" : "=l"(h0) : "r"(hadr + i * 8 + 0));
            asm volatile("ld.shared.b64 %0, [%1];" : "=l"(h1) : "r"(hadr + i * 8 + 8));
            asm volatile("ld.shared.b64 %0, [%1];" : "=l"(h2) : "r"(hadr + i * 8 + 16));
            asm volatile("ld.shared.b64 %0, [%1];" : "=l"(h3) : "r"(hadr + i * 8 + 24));
            asm("fma.rn.f32x2 %0, %1, %2, %3;" : "=l"(a0) : "l"(w[i + 0]), "l"(h0), "l"(a0));
            asm("fma.rn.f32x2 %0, %1, %2, %3;" : "=l"(a1) : "l"(w[i + 1]), "l"(h1), "l"(a1));
            asm("fma.rn.f32x2 %0, %1, %2, %3;" : "=l"(a2) : "l"(w[i + 2]), "l"(h2), "l"(a2));
            asm("fma.rn.f32x2 %0, %1, %2, %3;" : "=l"(a3) : "l"(w[i + 3]), "l"(h3), "l"(a3));
        }
        float x0, y0, x1, y1, x2, y2, x3, y3;
        asm("mov.b64 {%0, %1}, %2;" : "=f"(x0), "=f"(y0) : "l"(a0));
        asm("mov.b64 {%0, %1}, %2;" : "=f"(x1), "=f"(y1) : "l"(a1));
        asm("mov.b64 {%0, %1}, %2;" : "=f"(x2), "=f"(y2) : "l"(a2));
        asm("mov.b64 {%0, %1}, %2;" : "=f"(x3), "=f"(y3) : "l"(a3));
        float v = gcur + ((x0 + y0) + (x1 + y1)) + ((x2 + y2) + (x3 + y3));

        // ---- all-to-all gate broadcast into double-buffered exchange ----
        int par = s & 1;
        asm volatile("st.shared::cluster.f32 [%0], %1;" :: "r"(gadr[par][0]), "f"(v) : "memory");
        asm volatile("st.shared::cluster.f32 [%0], %1;" :: "r"(gadr[par][1]), "f"(v) : "memory");
        asm volatile("st.shared::cluster.f32 [%0], %1;" :: "r"(gadr[par][2]), "f"(v) : "memory");
        asm volatile("st.shared::cluster.f32 [%0], %1;" :: "r"(gadr[par][3]), "f"(v) : "memory");

        // ---- prefetch next step's gin while the barrier drains ----
        float gnext = 0.f;
        if (s + 1 < TT) gnext = gp[(size_t)(t + tstep) * 1024];

        asm volatile("barrier.cluster.arrive.aligned;" ::: "memory");
        asm volatile("barrier.cluster.wait.aligned;" ::: "memory");

        // ---- (c, h) update: identical in every CTA of the cluster ----
        float ig = sigmoidf_(gb[par][tid]);
        float fg = sigmoidf_(gb[par][tid + 128]);
        float gg = tanhf(gb[par][tid + 256]);
        float og = sigmoidf_(gb[par][tid + 384]);
        c = fg * c + ig * gg;
        float h = og * tanhf(c);
        hsh[tid] = h;
        if (rank == 0)
            hout[((size_t)b * TT + t) * 256 + d * HH + tid] = h;
        __syncthreads();

        t += tstep;
        gcur = gnext;
    }
}

// ---------------- mean over nodes ----------------
__global__ void agg_kernel(const float* __restrict__ lo, float* __restrict__ agg) {
    int b = blockIdx.x, o = threadIdx.x;
    float s = 0.f;
    const float* lb = lo + (size_t)b * TT * 256 + o;
    #pragma unroll 4
    for (int t = 0; t < TT; t++) s += lb[(size_t)t * 256];
    agg[b * 256 + o] = s * (1.0f / 256.0f);
}

// ---------------- host launcher ----------------
extern "C" void kernel_launch(void* const* d_in, const int* in_sizes, int n_in,
                              void* d_out, int out_size)
{
    const float* x         = (const float*)d_in[0];
    const float* cheb_w    = (const float*)d_in[5];   // [2,256,256]
    const float* cheb_b    = (const float*)d_in[6];
    const float* ln_cheb_g = (const float*)d_in[7];
    const float* ln_cheb_b = (const float*)d_in[8];
    const float* w_ih      = (const float*)d_in[9];   // [2,2,512,256]
    const float* w_hh      = (const float*)d_in[10];  // [2,2,512,128]
    const float* b_ih      = (const float*)d_in[11];  // [2,2,512]
    const float* b_hh      = (const float*)d_in[12];
    const float* ln_out_g  = (const float*)d_in[13];
    const float* ln_out_b  = (const float*)d_in[14];

    float* out = (float*)d_out;
    float* agg = out;                          // [8,256]
    float* tg  = out + BB * 256;               // [8,256,256]
    float* lo  = tg + BB * NN * NN;            // [8,256,256]

    float *S, *pk1, *ctmp, *cout, *gin, *h1, *h2;
    cudaGetSymbolAddress((void**)&S,    g_S);
    cudaGetSymbolAddress((void**)&pk1,  g_pk1);
    cudaGetSymbolAddress((void**)&ctmp, g_ctmp);
    cudaGetSymbolAddress((void**)&cout, g_cout);
    cudaGetSymbolAddress((void**)&gin,  g_gin);
    cudaGetSymbolAddress((void**)&h1,   g_h1);
    cudaGetSymbolAddress((void**)&h2,   g_h2);

    // TG output: exact constant (LayerNorm(1) degenerates; softmax of const rows)
    fill_tg_kernel<<<2048, 256>>>(tg);

    // ChebConv: out = x@W0 + ((x + S/256)/2)@W1 + cheb_b, then LN
    colsum_kernel<<<BB, FF>>>(x, S);
    pk1_kernel<<<1024, 512>>>(x, S, pk1);
    gemm64_kernel<false, false><<<dim3(FF/64, ROWS/64), 256>>>(
        x, cheb_w, ctmp, ROWS, FF, FF, nullptr, nullptr);
    gemm64_kernel<false, true><<<dim3(FF/64, ROWS/64), 256>>>(
        pk1, cheb_w + FF * FF, ctmp, ROWS, FF, FF, cheb_b, nullptr);
    ln256_kernel<<<ROWS, 256>>>(ctmp, ln_cheb_g, ln_cheb_b, cout);

    // Layer 1: both-dir input gates in ONE GEMM (w_ih dirs contiguous -> [1024,256])
    gemm64_kernel<true, false><<<dim3(1024/64, ROWS/64), 256>>>(
        cout, w_ih, gin, ROWS, 1024, FF, b_ih, b_hh);
    lstm_scan_cluster<<<64, 128>>>(gin, w_hh, h1);

    // Layer 2
    gemm64_kernel<true, false><<<dim3(1024/64, ROWS/64), 256>>>(
        h1, w_ih + (size_t)2 * G4 * FF, gin, ROWS, 1024, 2 * HH,
        b_ih + 2 * G4, b_hh + 2 * G4);
    lstm_scan_cluster<<<64, 128>>>(gin, w_hh + (size_t)2 * G4 * HH, h2);

    // Final LN -> lstm_out, then node-mean -> agg
    ln256_kernel<<<ROWS, 256>>>(h2, ln_out_g, ln_out_b, lo);
    agg_kernel<<<BB, 256>>>(lo, agg);
}

// round 6
// speedup vs baseline: 2.1264x; 1.3348x over previous
#include <cuda_runtime.h>
#include <cuda_bf16.h>
#include <cstdint>
#include <math.h>

// Problem constants
#define BB 8
#define NN 256
#define FF 256
#define HH 128
#define TT 256
#define G4 512           // 4*H gates
#define ROWS (BB*NN)     // 2048

// ---------------- scratch (device globals; no allocation allowed) ----------------
__device__ float g_S[BB*FF];                 // column sums
__device__ float g_pk1[BB*NN*FF];            // P @ x
__device__ float g_ctmp[BB*NN*FF];           // cheb pre-LN
__device__ float g_cout[BB*NN*FF];           // cheb out (layer1 input)
__device__ float g_gin[ROWS*1024];           // input gates, both dirs: [B*T][1024]
__device__ float g_h1[BB*NN*2*HH];           // layer1 concat output
__device__ float g_h2[BB*NN*2*HH];           // layer2 concat output

// ---------------- small helpers ----------------
__device__ __forceinline__ float blocksum256(float v, volatile float* red) {
    #pragma unroll
    for (int o = 16; o; o >>= 1) v += __shfl_xor_sync(0xffffffffu, v, o);
    if ((threadIdx.x & 31) == 0) red[threadIdx.x >> 5] = v;
    __syncthreads();
    float s = 0.f;
    #pragma unroll
    for (int i = 0; i < 8; i++) s += red[i];
    return s;
}

__device__ __forceinline__ unsigned smem_u32(const void* p) {
    unsigned a;
    asm("{ .reg .u64 t; cvta.to.shared.u64 t, %1; cvt.u32.u64 %0, t; }"
        : "=r"(a) : "l"(p));
    return a;
}

__device__ __forceinline__ float sigmoidf_(float x) {
    return 1.0f / (1.0f + expf(-x));
}

#define MBAR_INIT(adr, cnt) \
    asm volatile("mbarrier.init.shared.b64 [%0], %1;" :: "r"(adr), "r"(cnt) : "memory")

#define MBAR_EXPECT_TX(adr, bytes) \
    asm volatile("mbarrier.arrive.expect_tx.shared.b64 _, [%0], %1;" \
                 :: "r"(adr), "r"(bytes) : "memory")

#define MBAR_WAIT_PARITY(adr, parity) do {                                        \
    unsigned _done;                                                               \
    asm volatile("{\n\t.reg .pred p;\n\t"                                         \
        "mbarrier.try_wait.parity.acquire.cluster.shared::cta.b64 p, [%1], %2;\n\t" \
        "selp.b32 %0, 1, 0, p;\n\t}"                                              \
        : "=r"(_done) : "r"(adr), "r"(parity) : "memory");                        \
    while (!_done) {                                                              \
        asm volatile("{\n\t.reg .pred p;\n\t"                                     \
            "mbarrier.try_wait.parity.acquire.cluster.shared::cta.b64 p, [%1], %2, 0x989680;\n\t" \
            "selp.b32 %0, 1, 0, p;\n\t}"                                          \
            : "=r"(_done) : "r"(adr), "r"(parity) : "memory");                    \
    } } while (0)

// ---------------- trivial kernels ----------------
__global__ void fill_tg_kernel(float* __restrict__ tg) {
    int i = blockIdx.x * blockDim.x + threadIdx.x;
    if (i < BB*NN*NN) tg[i] = 1.0f / 256.0f;   // exact: softmax of constant rows
}

__global__ void colsum_kernel(const float* __restrict__ x, float* __restrict__ S) {
    int b = blockIdx.x, f = threadIdx.x;
    float s = 0.f;
    const float* xb = x + (size_t)b * NN * FF + f;
    #pragma unroll 4
    for (int n = 0; n < NN; n++) s += xb[(size_t)n * FF];
    S[b * FF + f] = s;
}

__global__ void pk1_kernel(const float* __restrict__ x, const float* __restrict__ S,
                           float* __restrict__ p) {
    int i = blockIdx.x * blockDim.x + threadIdx.x;
    if (i >= BB*NN*FF) return;
    int b = i >> 16;
    int f = i & (FF - 1);
    p[i] = 0.5f * (x[i] + (1.0f / 256.0f) * S[b * FF + f]);
}

// ---------------- fp32 GEMM, double-buffered smem, f32x2 accumulate ----------
// C[M,N] = A[M,K] @ B (+biases). BT: B is [N,K] (C=A@B^T). DUAL: K=512 split as
// A (k<256, stride 256) then A2 (k>=256, stride 256) — fuses the two cheb GEMMs.
template<bool BT, bool DUAL>
__global__ __launch_bounds__(256)
void gemm_db(const float* __restrict__ A, const float* __restrict__ A2,
             const float* __restrict__ B, float* __restrict__ C,
             int M, int N, int K,
             const float* __restrict__ bias0, const float* __restrict__ bias1)
{
    const int BK = 16;
    __shared__ float As[2][BK][64];
    __shared__ float Bs[2][BK][64];
    int tid = threadIdx.x;
    int tx = tid & 15, ty = tid >> 4;
    int bm = blockIdx.y * 64, bn = blockIdx.x * 64;

    int r  = tid >> 2, kq = (tid & 3) * 4;   // A / B-transposed loads
    int kr = tid >> 4, cq = (tid & 15) * 4;  // B (non-transposed) loads

    auto loadA = [&](int k0) -> float4 {
        const float* src = A; int kk = k0; int stride = K;
        if (DUAL) { stride = 256; if (k0 >= 256) { src = A2; kk = k0 - 256; } }
        return *(const float4*)(src + (size_t)(bm + r) * stride + kk + kq);
    };
    auto loadB = [&](int k0) -> float4 {
        if (BT) return *(const float4*)(B + (size_t)(bn + r) * K + k0 + kq);
        else    return *(const float4*)(B + (size_t)(k0 + kr) * N + bn + cq);
    };
    auto stash = [&](int st, float4 a, float4 bv) {
        As[st][kq + 0][r] = a.x; As[st][kq + 1][r] = a.y;
        As[st][kq + 2][r] = a.z; As[st][kq + 3][r] = a.w;
        if (BT) {
            Bs[st][kq + 0][r] = bv.x; Bs[st][kq + 1][r] = bv.y;
            Bs[st][kq + 2][r] = bv.z; Bs[st][kq + 3][r] = bv.w;
        } else {
            *(float4*)&Bs[st][kr][cq] = bv;
        }
    };

    const int ntiles = K / BK;
    stash(0, loadA(0), loadB(0));
    __syncthreads();

    unsigned long long acc[2][4];
    #pragma unroll
    for (int i = 0; i < 2; i++)
        #pragma unroll
        for (int j = 0; j < 4; j++) acc[i][j] = 0ull;

    for (int kt = 0; kt < ntiles; kt++) {
        int st = kt & 1;
        float4 an, bn2;
        if (kt + 1 < ntiles) { an = loadA((kt + 1) * BK); bn2 = loadB((kt + 1) * BK); }
        #pragma unroll
        for (int k = 0; k < BK; k++) {
            unsigned long long arp0 = *(const unsigned long long*)&As[st][k][ty * 4];
            unsigned long long arp1 = *(const unsigned long long*)&As[st][k][ty * 4 + 2];
            float bf0 = Bs[st][k][tx * 4 + 0], bf1 = Bs[st][k][tx * 4 + 1];
            float bf2 = Bs[st][k][tx * 4 + 2], bf3 = Bs[st][k][tx * 4 + 3];
            unsigned long long bd0, bd1, bd2, bd3;
            asm("mov.b64 %0, {%1, %1};" : "=l"(bd0) : "f"(bf0));
            asm("mov.b64 %0, {%1, %1};" : "=l"(bd1) : "f"(bf1));
            asm("mov.b64 %0, {%1, %1};" : "=l"(bd2) : "f"(bf2));
            asm("mov.b64 %0, {%1, %1};" : "=l"(bd3) : "f"(bf3));
            asm("fma.rn.f32x2 %0, %1, %2, %3;" : "=l"(acc[0][0]) : "l"(arp0), "l"(bd0), "l"(acc[0][0]));
            asm("fma.rn.f32x2 %0, %1, %2, %3;" : "=l"(acc[0][1]) : "l"(arp0), "l"(bd1), "l"(acc[0][1]));
            asm("fma.rn.f32x2 %0, %1, %2, %3;" : "=l"(acc[0][2]) : "l"(arp0), "l"(bd2), "l"(acc[0][2]));
            asm("fma.rn.f32x2 %0, %1, %2, %3;" : "=l"(acc[0][3]) : "l"(arp0), "l"(bd3), "l"(acc[0][3]));
            asm("fma.rn.f32x2 %0, %1, %2, %3;" : "=l"(acc[1][0]) : "l"(arp1), "l"(bd0), "l"(acc[1][0]));
            asm("fma.rn.f32x2 %0, %1, %2, %3;" : "=l"(acc[1][1]) : "l"(arp1), "l"(bd1), "l"(acc[1][1]));
            asm("fma.rn.f32x2 %0, %1, %2, %3;" : "=l"(acc[1][2]) : "l"(arp1), "l"(bd2), "l"(acc[1][2]));
            asm("fma.rn.f32x2 %0, %1, %2, %3;" : "=l"(acc[1][3]) : "l"(arp1), "l"(bd3), "l"(acc[1][3]));
        }
        if (kt + 1 < ntiles) stash(st ^ 1, an, bn2);
        __syncthreads();
    }

    // epilogue: acc[i][j] lo = row 4ty+2i, hi = row 4ty+2i+1; col = bn + tx*4 + j
    #pragma unroll
    for (int i = 0; i < 2; i++) {
        float v[2][4];
        #pragma unroll
        for (int j = 0; j < 4; j++) {
            float lo, hi;
            asm("mov.b64 {%0, %1}, %2;" : "=f"(lo), "=f"(hi) : "l"(acc[i][j]));
            v[0][j] = lo; v[1][j] = hi;
        }
        #pragma unroll
        for (int ii = 0; ii < 2; ii++) {
            int row = bm + ty * 4 + i * 2 + ii;
            int col = bn + tx * 4;
            float4 o = make_float4(v[ii][0], v[ii][1], v[ii][2], v[ii][3]);
            if (bias0) {
                o.x += bias0[col];     o.y += bias0[col + 1];
                o.z += bias0[col + 2]; o.w += bias0[col + 3];
            }
            if (bias1) {
                o.x += bias1[col];     o.y += bias1[col + 1];
                o.z += bias1[col + 2]; o.w += bias1[col + 3];
            }
            *(float4*)(C + (size_t)row * N + col) = o;
        }
    }
}

// ---------------- LayerNorm over 256 elems per row ----------------
__global__ __launch_bounds__(256)
void ln256_kernel(const float* __restrict__ x, const float* __restrict__ g,
                  const float* __restrict__ bt, float* __restrict__ y)
{
    __shared__ float red1[8];
    __shared__ float red2[8];
    size_t row = blockIdx.x;
    float v = x[row * 256 + threadIdx.x];
    float m = blocksum256(v, red1) * (1.0f / 256.0f);
    float d = v - m;
    float var = blocksum256(d * d, red2) * (1.0f / 256.0f);
    float r = rsqrtf(var + 1e-5f);
    y[row * 256 + threadIdx.x] = d * r * g[threadIdx.x] + bt[threadIdx.x];
}

// ---------------- LSTM scan: register-resident Whh, 4-CTA clusters ----------------
// One cluster of 4 CTAs per (batch, dir). CTA rank r owns gates [r*128, r*128+128).
// Per step: dot(W_row, h) via fma.rn.f32x2 -> st.async gate broadcast to all 4
// CTAs completing on remote mbar[par] (expect_tx = 2048 bytes = 512 gates) ->
// try_wait.parity.acquire.cluster -> each CTA redundantly computes (c, h).
// Expect/tx race safety: tid0 issues expect(s+2) right after wait(s); any
// producer's step-s+2 store is gated (via its wait(s+1)) on tid0's own step-s+1
// store, which is after the expect. Initial expects precede the cluster barrier.
__global__ void __launch_bounds__(128, 1) __cluster_dims__(4, 1, 1)
lstm_scan_cluster(const float* __restrict__ gin, const float* __restrict__ whh,
                  float* __restrict__ hout)
{
    __shared__ __align__(16) float hsh[HH];
    __shared__ __align__(16) float gb[2][G4];
    __shared__ __align__(8) unsigned long long mbar[2];

    int tid = threadIdx.x;
    unsigned rank;
    asm("mov.u32 %0, %%cluster_ctarank;" : "=r"(rank));
    int pair = blockIdx.x >> 2;
    int b = pair >> 1, d = pair & 1;
    int gate = (int)rank * 128 + tid;

    // ---- load this thread's Whh row into registers (64 f32x2 pairs) ----
    unsigned long long w[64];
    const float2* wrow = (const float2*)(whh + ((size_t)d * G4 + gate) * HH);
    #pragma unroll
    for (int i = 0; i < 64; i++) {
        float2 t2 = wrow[i];
        asm("mov.b64 %0, {%1, %2};" : "=l"(w[i]) : "f"(t2.x), "f"(t2.y));
    }

    const float* gp = gin + ((size_t)b * TT) * 1024 + d * 512 + gate;

    hsh[tid] = 0.f;

    unsigned hadr = smem_u32(hsh);
    unsigned mloc[2] = { smem_u32(&mbar[0]), smem_u32(&mbar[1]) };
    unsigned gadr[2][4], madr[2][4];
    #pragma unroll
    for (int par = 0; par < 2; par++) {
        unsigned la = smem_u32(&gb[par][gate]);
        #pragma unroll
        for (int peer = 0; peer < 4; peer++) {
            asm("mapa.shared::cluster.u32 %0, %1, %2;"
                : "=r"(gadr[par][peer]) : "r"(la), "r"(peer));
            asm("mapa.shared::cluster.u32 %0, %1, %2;"
                : "=r"(madr[par][peer]) : "r"(mloc[par]), "r"(peer));
        }
    }

    if (tid == 0) {
        MBAR_INIT(mloc[0], 1);
        MBAR_INIT(mloc[1], 1);
        MBAR_EXPECT_TX(mloc[0], 2048);   // step 0
        MBAR_EXPECT_TX(mloc[1], 2048);   // step 1
    }
    __syncthreads();
    // cluster barrier: inits+expects visible before any peer st.async
    asm volatile("barrier.cluster.arrive.aligned;" ::: "memory");
    asm volatile("barrier.cluster.wait.aligned;" ::: "memory");

    int ph0 = 0, ph1 = 0;
    float c = 0.f;
    int t = d ? (TT - 1) : 0;
    const int tstep = d ? -1 : 1;
    float gcur = gp[(size_t)t * 1024];

    for (int s = 0; s < TT; s++) {
        // ---- dot(W_row, h): volatile LDS (hsh mutates) + packed FMAs ----
        unsigned long long a0 = 0ull, a1 = 0ull, a2 = 0ull, a3 = 0ull;
        #pragma unroll
        for (int i = 0; i < 64; i += 4) {
            unsigned long long h0, h1, h2, h3;
            asm volatile("ld.shared.b64 %0, [%1];" : "=l"(h0) : "r"(hadr + i * 8 + 0));
            asm volatile("ld.shared.b64 %0, [%1];" : "=l"(h1) : "r"(hadr + i * 8 + 8));
            asm volatile("ld.shared.b64 %0, [%1];" : "=l"(h2) : "r"(hadr + i * 8 + 16));
            asm volatile("ld.shared.b64 %0, [%1];" : "=l"(h3) : "r"(hadr + i * 8 + 24));
            asm("fma.rn.f32x2 %0, %1, %2, %3;" : "=l"(a0) : "l"(w[i + 0]), "l"(h0), "l"(a0));
            asm("fma.rn.f32x2 %0, %1, %2, %3;" : "=l"(a1) : "l"(w[i + 1]), "l"(h1), "l"(a1));
            asm("fma.rn.f32x2 %0, %1, %2, %3;" : "=l"(a2) : "l"(w[i + 2]), "l"(h2), "l"(a2));
            asm("fma.rn.f32x2 %0, %1, %2, %3;" : "=l"(a3) : "l"(w[i + 3]), "l"(h3), "l"(a3));
        }
        float x0, y0, x1, y1, x2, y2, x3, y3;
        asm("mov.b64 {%0, %1}, %2;" : "=f"(x0), "=f"(y0) : "l"(a0));
        asm("mov.b64 {%0, %1}, %2;" : "=f"(x1), "=f"(y1) : "l"(a1));
        asm("mov.b64 {%0, %1}, %2;" : "=f"(x2), "=f"(y2) : "l"(a2));
        asm("mov.b64 {%0, %1}, %2;" : "=f"(x3), "=f"(y3) : "l"(a3));
        float v = gcur + ((x0 + y0) + (x1 + y1)) + ((x2 + y2) + (x3 + y3));

        // ---- async gate broadcast: tx-counted remote stores ----
        int par = s & 1;
        unsigned vbits = __float_as_uint(v);
        #pragma unroll
        for (int peer = 0; peer < 4; peer++) {
            asm volatile(
                "st.async.shared::cluster.mbarrier::complete_tx::bytes.b32 [%0], %1, [%2];"
                :: "r"(gadr[par][peer]), "r"(vbits), "r"(madr[par][peer]) : "memory");
        }

        // ---- prefetch next step's gin while stores fly ----
        float gnext = 0.f;
        if (s + 1 < TT) gnext = gp[(size_t)(t + tstep) * 1024];

        __syncthreads();   // all local hsh reads done before the update writes

        unsigned mb = par ? mloc[1] : mloc[0];
        int phv = par ? ph1 : ph0;
        MBAR_WAIT_PARITY(mb, phv);
        if (par) ph1 ^= 1; else ph0 ^= 1;
        if (tid == 0 && s + 2 < TT) MBAR_EXPECT_TX(mb, 2048);

        // ---- (c, h) update: identical in every CTA of the cluster ----
        float ig = sigmoidf_(gb[par][tid]);
        float fg = sigmoidf_(gb[par][tid + 128]);
        float gg = tanhf(gb[par][tid + 256]);
        float og = sigmoidf_(gb[par][tid + 384]);
        c = fg * c + ig * gg;
        float h = og * tanhf(c);
        hsh[tid] = h;
        if (rank == 0)
            hout[((size_t)b * TT + t) * 256 + d * HH + tid] = h;
        __syncthreads();

        t += tstep;
        gcur = gnext;
    }

    // no CTA may exit while peers' st.async targeting it are in flight
    asm volatile("barrier.cluster.arrive.aligned;" ::: "memory");
    asm volatile("barrier.cluster.wait.aligned;" ::: "memory");
}

// ---------------- mean over nodes ----------------
__global__ void agg_kernel(const float* __restrict__ lo, float* __restrict__ agg) {
    int b = blockIdx.x, o = threadIdx.x;
    float s = 0.f;
    const float* lb = lo + (size_t)b * TT * 256 + o;
    #pragma unroll 4
    for (int t = 0; t < TT; t++) s += lb[(size_t)t * 256];
    agg[b * 256 + o] = s * (1.0f / 256.0f);
}

// ---------------- host launcher ----------------
extern "C" void kernel_launch(void* const* d_in, const int* in_sizes, int n_in,
                              void* d_out, int out_size)
{
    const float* x         = (const float*)d_in[0];
    const float* cheb_w    = (const float*)d_in[5];   // [2,256,256] = [512,256] stacked
    const float* cheb_b    = (const float*)d_in[6];
    const float* ln_cheb_g = (const float*)d_in[7];
    const float* ln_cheb_b = (const float*)d_in[8];
    const float* w_ih      = (const float*)d_in[9];   // [2,2,512,256]
    const float* w_hh      = (const float*)d_in[10];  // [2,2,512,128]
    const float* b_ih      = (const float*)d_in[11];  // [2,2,512]
    const float* b_hh      = (const float*)d_in[12];
    const float* ln_out_g  = (const float*)d_in[13];
    const float* ln_out_b  = (const float*)d_in[14];

    float* out = (float*)d_out;
    float* agg = out;                          // [8,256]
    float* tg  = out + BB * 256;               // [8,256,256]
    float* lo  = tg + BB * NN * NN;            // [8,256,256]

    float *S, *pk1, *ctmp, *cout, *gin, *h1, *h2;
    cudaGetSymbolAddress((void**)&S,    g_S);
    cudaGetSymbolAddress((void**)&pk1,  g_pk1);
    cudaGetSymbolAddress((void**)&ctmp, g_ctmp);
    cudaGetSymbolAddress((void**)&cout, g_cout);
    cudaGetSymbolAddress((void**)&gin,  g_gin);
    cudaGetSymbolAddress((void**)&h1,   g_h1);
    cudaGetSymbolAddress((void**)&h2,   g_h2);

    // TG output: exact constant (LayerNorm(1) degenerates; softmax of const rows)
    fill_tg_kernel<<<2048, 256>>>(tg);

    // ChebConv: ctmp = [x | pk1] @ [W0;W1] + cheb_b  (single fused K=512 GEMM)
    colsum_kernel<<<BB, FF>>>(x, S);
    pk1_kernel<<<1024, 512>>>(x, S, pk1);
    gemm_db<false, true><<<dim3(FF/64, ROWS/64), 256>>>(
        x, pk1, cheb_w, ctmp, ROWS, FF, 512, cheb_b, nullptr);
    ln256_kernel<<<ROWS, 256>>>(ctmp, ln_cheb_g, ln_cheb_b, cout);

    // Layer 1: both-dir input gates in ONE GEMM (w_ih dirs contiguous -> [1024,256])
    gemm_db<true, false><<<dim3(1024/64, ROWS/64), 256>>>(
        cout, nullptr, w_ih, gin, ROWS, 1024, FF, b_ih, b_hh);
    lstm_scan_cluster<<<64, 128>>>(gin, w_hh, h1);

    // Layer 2
    gemm_db<true, false><<<dim3(1024/64, ROWS/64), 256>>>(
        h1, nullptr, w_ih + (size_t)2 * G4 * FF, gin, ROWS, 1024, 2 * HH,
        b_ih + 2 * G4, b_hh + 2 * G4);
    lstm_scan_cluster<<<64, 128>>>(gin, w_hh + (size_t)2 * G4 * HH, h2);

    // Final LN -> lstm_out, then node-mean -> agg
    ln256_kernel<<<ROWS, 256>>>(h2, ln_out_g, ln_out_b, lo);
    agg_kernel<<<BB, 256>>>(lo, agg);
}

// round 7
// speedup vs baseline: 2.6487x; 1.2457x over previous
#include <cuda_runtime.h>
#include <cuda_bf16.h>
#include <cstdint>
#include <math.h>

// Problem constants
#define BB 8
#define NN 256
#define FF 256
#define HH 128
#define TT 256
#define G4 512           // 4*H gates
#define ROWS (BB*NN)     // 2048

// ---------------- scratch (device globals; no allocation allowed) ----------------
__device__ float g_S[BB*FF];                 // column sums
__device__ float g_ctmp[BB*NN*FF];           // cheb pre-LN
__device__ float g_cout[BB*NN*FF];           // cheb out (layer1 input)
__device__ float g_gin[ROWS*1024];           // input gates, both dirs: [B*T][1024]
__device__ float g_h1[BB*NN*2*HH];           // layer1 concat output
__device__ float g_h2[BB*NN*2*HH];           // layer2 concat output

// ---------------- small helpers ----------------
__device__ __forceinline__ float blocksum256(float v, volatile float* red) {
    #pragma unroll
    for (int o = 16; o; o >>= 1) v += __shfl_xor_sync(0xffffffffu, v, o);
    if ((threadIdx.x & 31) == 0) red[threadIdx.x >> 5] = v;
    __syncthreads();
    float s = 0.f;
    #pragma unroll
    for (int i = 0; i < 8; i++) s += red[i];
    return s;
}

__device__ __forceinline__ unsigned smem_u32(const void* p) {
    unsigned a;
    asm("{ .reg .u64 t; cvta.to.shared.u64 t, %1; cvt.u32.u64 %0, t; }"
        : "=r"(a) : "l"(p));
    return a;
}

// fast activations: __expf/__fdividef (rel err ~1e-7, fine vs 1e-3 threshold)
__device__ __forceinline__ float fsigmoid(float x) {
    return __fdividef(1.0f, 1.0f + __expf(-x));
}
__device__ __forceinline__ float ftanh(float x) {
    // 1 - 2/(e^{2x}+1); inf-safe at both ends
    return 1.0f - __fdividef(2.0f, __expf(2.0f * x) + 1.0f);
}

#define MBAR_INIT(adr, cnt) \
    asm volatile("mbarrier.init.shared.b64 [%0], %1;" :: "r"(adr), "r"(cnt) : "memory")

#define MBAR_EXPECT_TX(adr, bytes) \
    asm volatile("mbarrier.arrive.expect_tx.shared.b64 _, [%0], %1;" \
                 :: "r"(adr), "r"(bytes) : "memory")

#define MBAR_WAIT_PARITY(adr, parity) do {                                        \
    unsigned _done;                                                               \
    asm volatile("{\n\t.reg .pred p;\n\t"                                         \
        "mbarrier.try_wait.parity.acquire.cluster.shared::cta.b64 p, [%1], %2;\n\t" \
        "selp.b32 %0, 1, 0, p;\n\t}"                                              \
        : "=r"(_done) : "r"(adr), "r"(parity) : "memory");                        \
    while (!_done) {                                                              \
        asm volatile("{\n\t.reg .pred p;\n\t"                                     \
            "mbarrier.try_wait.parity.acquire.cluster.shared::cta.b64 p, [%1], %2, 0x989680;\n\t" \
            "selp.b32 %0, 1, 0, p;\n\t}"                                          \
            : "=r"(_done) : "r"(adr), "r"(parity) : "memory");                    \
    } } while (0)

// ---------------- colsum + TG fill (merged launch) ----------------
__global__ void colsum_fill_kernel(const float* __restrict__ x, float* __restrict__ S,
                                   float* __restrict__ tg) {
    if (blockIdx.x < BB) {
        int b = blockIdx.x, f = threadIdx.x;
        float s = 0.f;
        const float* xb = x + (size_t)b * NN * FF + f;
        #pragma unroll 4
        for (int n = 0; n < NN; n++) s += xb[(size_t)n * FF];
        S[b * FF + f] = s;
    } else {
        // TG = exact constant (LayerNorm(1) degenerates; softmax of const rows)
        int i = (blockIdx.x - BB) * blockDim.x + threadIdx.x;
        const float q = 1.0f / 256.0f;
        ((float4*)tg)[i] = make_float4(q, q, q, q);
    }
}

// ---------------- fp32 GEMM, double-buffered smem, f32x2 accumulate ----------
// C[M,N] = A[M,K] @ B (+biases). BT: B is [N,K] (C=A@B^T). DUAL: K=512 fused
// cheb GEMM: k<256 reads x; k>=256 computes 0.5*(x + S/256) on the fly (A2=S).
template<bool BT, bool DUAL>
__global__ __launch_bounds__(256)
void gemm_db(const float* __restrict__ A, const float* __restrict__ A2,
             const float* __restrict__ B, float* __restrict__ C,
             int M, int N, int K,
             const float* __restrict__ bias0, const float* __restrict__ bias1)
{
    const int BK = 16;
    __shared__ float As[2][BK][64];
    __shared__ float Bs[2][BK][64];
    int tid = threadIdx.x;
    int tx = tid & 15, ty = tid >> 4;
    int bm = blockIdx.y * 64, bn = blockIdx.x * 64;

    int r  = tid >> 2, kq = (tid & 3) * 4;   // A / B-transposed loads
    int kr = tid >> 4, cq = (tid & 15) * 4;  // B (non-transposed) loads

    auto loadA = [&](int k0) -> float4 {
        if (DUAL) {
            if (k0 >= 256) {
                int kk = k0 - 256;
                float4 xv = *(const float4*)(A + (size_t)(bm + r) * 256 + kk + kq);
                const float* sb = A2 + ((bm + r) >> 8) * 256 + kk + kq;
                float4 sv = *(const float4*)sb;
                const float q = 1.0f / 256.0f;
                return make_float4(0.5f * (xv.x + q * sv.x), 0.5f * (xv.y + q * sv.y),
                                   0.5f * (xv.z + q * sv.z), 0.5f * (xv.w + q * sv.w));
            }
            return *(const float4*)(A + (size_t)(bm + r) * 256 + k0 + kq);
        }
        return *(const float4*)(A + (size_t)(bm + r) * K + k0 + kq);
    };
    auto loadB = [&](int k0) -> float4 {
        if (BT) return *(const float4*)(B + (size_t)(bn + r) * K + k0 + kq);
        else    return *(const float4*)(B + (size_t)(k0 + kr) * N + bn + cq);
    };
    auto stash = [&](int st, float4 a, float4 bv) {
        As[st][kq + 0][r] = a.x; As[st][kq + 1][r] = a.y;
        As[st][kq + 2][r] = a.z; As[st][kq + 3][r] = a.w;
        if (BT) {
            Bs[st][kq + 0][r] = bv.x; Bs[st][kq + 1][r] = bv.y;
            Bs[st][kq + 2][r] = bv.z; Bs[st][kq + 3][r] = bv.w;
        } else {
            *(float4*)&Bs[st][kr][cq] = bv;
        }
    };

    const int ntiles = K / BK;
    stash(0, loadA(0), loadB(0));
    __syncthreads();

    unsigned long long acc[2][4];
    #pragma unroll
    for (int i = 0; i < 2; i++)
        #pragma unroll
        for (int j = 0; j < 4; j++) acc[i][j] = 0ull;

    for (int kt = 0; kt < ntiles; kt++) {
        int st = kt & 1;
        float4 an, bn2;
        if (kt + 1 < ntiles) { an = loadA((kt + 1) * BK); bn2 = loadB((kt + 1) * BK); }
        #pragma unroll
        for (int k = 0; k < BK; k++) {
            unsigned long long arp0 = *(const unsigned long long*)&As[st][k][ty * 4];
            unsigned long long arp1 = *(const unsigned long long*)&As[st][k][ty * 4 + 2];
            float bf0 = Bs[st][k][tx * 4 + 0], bf1 = Bs[st][k][tx * 4 + 1];
            float bf2 = Bs[st][k][tx * 4 + 2], bf3 = Bs[st][k][tx * 4 + 3];
            unsigned long long bd0, bd1, bd2, bd3;
            asm("mov.b64 %0, {%1, %1};" : "=l"(bd0) : "f"(bf0));
            asm("mov.b64 %0, {%1, %1};" : "=l"(bd1) : "f"(bf1));
            asm("mov.b64 %0, {%1, %1};" : "=l"(bd2) : "f"(bf2));
            asm("mov.b64 %0, {%1, %1};" : "=l"(bd3) : "f"(bf3));
            asm("fma.rn.f32x2 %0, %1, %2, %3;" : "=l"(acc[0][0]) : "l"(arp0), "l"(bd0), "l"(acc[0][0]));
            asm("fma.rn.f32x2 %0, %1, %2, %3;" : "=l"(acc[0][1]) : "l"(arp0), "l"(bd1), "l"(acc[0][1]));
            asm("fma.rn.f32x2 %0, %1, %2, %3;" : "=l"(acc[0][2]) : "l"(arp0), "l"(bd2), "l"(acc[0][2]));
            asm("fma.rn.f32x2 %0, %1, %2, %3;" : "=l"(acc[0][3]) : "l"(arp0), "l"(bd3), "l"(acc[0][3]));
            asm("fma.rn.f32x2 %0, %1, %2, %3;" : "=l"(acc[1][0]) : "l"(arp1), "l"(bd0), "l"(acc[1][0]));
            asm("fma.rn.f32x2 %0, %1, %2, %3;" : "=l"(acc[1][1]) : "l"(arp1), "l"(bd1), "l"(acc[1][1]));
            asm("fma.rn.f32x2 %0, %1, %2, %3;" : "=l"(acc[1][2]) : "l"(arp1), "l"(bd2), "l"(acc[1][2]));
            asm("fma.rn.f32x2 %0, %1, %2, %3;" : "=l"(acc[1][3]) : "l"(arp1), "l"(bd3), "l"(acc[1][3]));
        }
        if (kt + 1 < ntiles) stash(st ^ 1, an, bn2);
        __syncthreads();
    }

    #pragma unroll
    for (int i = 0; i < 2; i++) {
        float v[2][4];
        #pragma unroll
        for (int j = 0; j < 4; j++) {
            float lo, hi;
            asm("mov.b64 {%0, %1}, %2;" : "=f"(lo), "=f"(hi) : "l"(acc[i][j]));
            v[0][j] = lo; v[1][j] = hi;
        }
        #pragma unroll
        for (int ii = 0; ii < 2; ii++) {
            int row = bm + ty * 4 + i * 2 + ii;
            int col = bn + tx * 4;
            float4 o = make_float4(v[ii][0], v[ii][1], v[ii][2], v[ii][3]);
            if (bias0) {
                o.x += bias0[col];     o.y += bias0[col + 1];
                o.z += bias0[col + 2]; o.w += bias0[col + 3];
            }
            if (bias1) {
                o.x += bias1[col];     o.y += bias1[col + 1];
                o.z += bias1[col + 2]; o.w += bias1[col + 3];
            }
            *(float4*)(C + (size_t)row * N + col) = o;
        }
    }
}

// ---------------- 128x128-tile GEMM for the gin GEMMs ----------------
// C[M,N] = A[M,K] @ B[N,K]^T + bias0 + bias1.  256 threads, 8x8 outputs each
// (f32x2-packed along rows): 32 FFMA2 per k per thread -> FMA-pipe-bound.
__global__ __launch_bounds__(256)
void gemm128t(const float* __restrict__ A, const float* __restrict__ B,
              float* __restrict__ C, int M, int N, int K,
              const float* __restrict__ bias0, const float* __restrict__ bias1)
{
    const int BK = 16;
    __shared__ float As[2][BK][128];
    __shared__ float Bs[2][BK][128];
    int tid = threadIdx.x;
    int tx = tid & 15, ty = tid >> 4;
    int bm = blockIdx.y * 128, bn = blockIdx.x * 128;

    // tile loads: q in {2*tid, 2*tid+1}; r = q>>2 (row), kf = (q&3)*4
    int r0 = (2 * tid) >> 2,     kf0 = ((2 * tid) & 3) * 4;
    int r1 = (2 * tid + 1) >> 2, kf1 = ((2 * tid + 1) & 3) * 4;

    auto loadA4 = [&](int k0, int rr, int kf) -> float4 {
        return *(const float4*)(A + (size_t)(bm + rr) * K + k0 + kf);
    };
    auto loadB4 = [&](int k0, int rr, int kf) -> float4 {
        return *(const float4*)(B + (size_t)(bn + rr) * K + k0 + kf);
    };
    auto stash = [&](int st, float4 a0, float4 a1, float4 b0, float4 b1) {
        As[st][kf0 + 0][r0] = a0.x; As[st][kf0 + 1][r0] = a0.y;
        As[st][kf0 + 2][r0] = a0.z; As[st][kf0 + 3][r0] = a0.w;
        As[st][kf1 + 0][r1] = a1.x; As[st][kf1 + 1][r1] = a1.y;
        As[st][kf1 + 2][r1] = a1.z; As[st][kf1 + 3][r1] = a1.w;
        Bs[st][kf0 + 0][r0] = b0.x; Bs[st][kf0 + 1][r0] = b0.y;
        Bs[st][kf0 + 2][r0] = b0.z; Bs[st][kf0 + 3][r0] = b0.w;
        Bs[st][kf1 + 0][r1] = b1.x; Bs[st][kf1 + 1][r1] = b1.y;
        Bs[st][kf1 + 2][r1] = b1.z; Bs[st][kf1 + 3][r1] = b1.w;
    };

    const int ntiles = K / BK;
    stash(0, loadA4(0, r0, kf0), loadA4(0, r1, kf1),
             loadB4(0, r0, kf0), loadB4(0, r1, kf1));
    __syncthreads();

    unsigned long long acc[4][8];
    #pragma unroll
    for (int i = 0; i < 4; i++)
        #pragma unroll
        for (int j = 0; j < 8; j++) acc[i][j] = 0ull;

    for (int kt = 0; kt < ntiles; kt++) {
        int st = kt & 1;
        float4 an0, an1, bn0, bn1;
        if (kt + 1 < ntiles) {
            int k0 = (kt + 1) * BK;
            an0 = loadA4(k0, r0, kf0); an1 = loadA4(k0, r1, kf1);
            bn0 = loadB4(k0, r0, kf0); bn1 = loadB4(k0, r1, kf1);
        }
        #pragma unroll
        for (int k = 0; k < BK; k++) {
            const float* ar = &As[st][k][ty * 8];
            const float* br = &Bs[st][k][tx * 8];
            unsigned long long ap[4], bd[8];
            #pragma unroll
            for (int i = 0; i < 4; i++) {
                float2 a2 = *(const float2*)(ar + 2 * i);
                asm("mov.b64 %0, {%1, %2};" : "=l"(ap[i]) : "f"(a2.x), "f"(a2.y));
            }
            #pragma unroll
            for (int i = 0; i < 4; i++) {
                float2 b2 = *(const float2*)(br + 2 * i);
                asm("mov.b64 %0, {%1, %1};" : "=l"(bd[2 * i])     : "f"(b2.x));
                asm("mov.b64 %0, {%1, %1};" : "=l"(bd[2 * i + 1]) : "f"(b2.y));
            }
            #pragma unroll
            for (int i = 0; i < 4; i++)
                #pragma unroll
                for (int j = 0; j < 8; j++)
                    asm("fma.rn.f32x2 %0, %1, %2, %3;"
                        : "=l"(acc[i][j]) : "l"(ap[i]), "l"(bd[j]), "l"(acc[i][j]));
        }
        if (kt + 1 < ntiles)
            stash(st ^ 1, an0, an1, bn0, bn1);
        __syncthreads();
    }

    // epilogue: acc[i][j] lo = row ty*8+2i, hi = row ty*8+2i+1; col = bn+tx*8+j
    float bsum[8];
    #pragma unroll
    for (int j = 0; j < 8; j++) {
        int col = bn + tx * 8 + j;
        bsum[j] = (bias0 ? bias0[col] : 0.f) + (bias1 ? bias1[col] : 0.f);
    }
    #pragma unroll
    for (int i = 0; i < 4; i++) {
        float lov[8], hiv[8];
        #pragma unroll
        for (int j = 0; j < 8; j++) {
            float lo, hi;
            asm("mov.b64 {%0, %1}, %2;" : "=f"(lo), "=f"(hi) : "l"(acc[i][j]));
            lov[j] = lo + bsum[j]; hiv[j] = hi + bsum[j];
        }
        int row = bm + ty * 8 + 2 * i;
        int col = bn + tx * 8;
        *(float4*)(C + (size_t)row * N + col)           = make_float4(lov[0], lov[1], lov[2], lov[3]);
        *(float4*)(C + (size_t)row * N + col + 4)       = make_float4(lov[4], lov[5], lov[6], lov[7]);
        *(float4*)(C + (size_t)(row + 1) * N + col)     = make_float4(hiv[0], hiv[1], hiv[2], hiv[3]);
        *(float4*)(C + (size_t)(row + 1) * N + col + 4) = make_float4(hiv[4], hiv[5], hiv[6], hiv[7]);
    }
}

// ---------------- LayerNorm over 256 elems per row ----------------
__global__ __launch_bounds__(256)
void ln256_kernel(const float* __restrict__ x, const float* __restrict__ g,
                  const float* __restrict__ bt, float* __restrict__ y)
{
    __shared__ float red1[8];
    __shared__ float red2[8];
    size_t row = blockIdx.x;
    float v = x[row * 256 + threadIdx.x];
    float m = blocksum256(v, red1) * (1.0f / 256.0f);
    float d = v - m;
    float var = blocksum256(d * d, red2) * (1.0f / 256.0f);
    float r = rsqrtf(var + 1e-5f);
    y[row * 256 + threadIdx.x] = d * r * g[threadIdx.x] + bt[threadIdx.x];
}

// ---------------- LSTM scan: register-resident Whh, 4-CTA clusters ----------------
// (see R6 comments; this round: v2.b64 h loads + fast activations)
__global__ void __launch_bounds__(128, 1) __cluster_dims__(4, 1, 1)
lstm_scan_cluster(const float* __restrict__ gin, const float* __restrict__ whh,
                  float* __restrict__ hout)
{
    __shared__ __align__(16) float hsh[HH];
    __shared__ __align__(16) float gb[2][G4];
    __shared__ __align__(8) unsigned long long mbar[2];

    int tid = threadIdx.x;
    unsigned rank;
    asm("mov.u32 %0, %%cluster_ctarank;" : "=r"(rank));
    int pair = blockIdx.x >> 2;
    int b = pair >> 1, d = pair & 1;
    int gate = (int)rank * 128 + tid;

    unsigned long long w[64];
    const float2* wrow = (const float2*)(whh + ((size_t)d * G4 + gate) * HH);
    #pragma unroll
    for (int i = 0; i < 64; i++) {
        float2 t2 = wrow[i];
        asm("mov.b64 %0, {%1, %2};" : "=l"(w[i]) : "f"(t2.x), "f"(t2.y));
    }

    const float* gp = gin + ((size_t)b * TT) * 1024 + d * 512 + gate;

    hsh[tid] = 0.f;

    unsigned hadr = smem_u32(hsh);
    unsigned mloc[2] = { smem_u32(&mbar[0]), smem_u32(&mbar[1]) };
    unsigned gadr[2][4], madr[2][4];
    #pragma unroll
    for (int par = 0; par < 2; par++) {
        unsigned la = smem_u32(&gb[par][gate]);
        #pragma unroll
        for (int peer = 0; peer < 4; peer++) {
            asm("mapa.shared::cluster.u32 %0, %1, %2;"
                : "=r"(gadr[par][peer]) : "r"(la), "r"(peer));
            asm("mapa.shared::cluster.u32 %0, %1, %2;"
                : "=r"(madr[par][peer]) : "r"(mloc[par]), "r"(peer));
        }
    }

    if (tid == 0) {
        MBAR_INIT(mloc[0], 1);
        MBAR_INIT(mloc[1], 1);
        MBAR_EXPECT_TX(mloc[0], 2048);   // step 0
        MBAR_EXPECT_TX(mloc[1], 2048);   // step 1
    }
    __syncthreads();
    asm volatile("barrier.cluster.arrive.aligned;" ::: "memory");
    asm volatile("barrier.cluster.wait.aligned;" ::: "memory");

    int ph0 = 0, ph1 = 0;
    float c = 0.f;
    int t = d ? (TT - 1) : 0;
    const int tstep = d ? -1 : 1;
    float gcur = gp[(size_t)t * 1024];

    for (int s = 0; s < TT; s++) {
        // ---- dot(W_row, h): volatile v2.b64 LDS + packed FMAs ----
        unsigned long long a0 = 0ull, a1 = 0ull, a2 = 0ull, a3 = 0ull;
        #pragma unroll
        for (int i = 0; i < 64; i += 4) {
            unsigned long long h0, h1, h2, h3;
            asm volatile("ld.shared.v2.b64 {%0, %1}, [%2];"
                         : "=l"(h0), "=l"(h1) : "r"(hadr + i * 8));
            asm volatile("ld.shared.v2.b64 {%0, %1}, [%2];"
                         : "=l"(h2), "=l"(h3) : "r"(hadr + i * 8 + 16));
            asm("fma.rn.f32x2 %0, %1, %2, %3;" : "=l"(a0) : "l"(w[i + 0]), "l"(h0), "l"(a0));
            asm("fma.rn.f32x2 %0, %1, %2, %3;" : "=l"(a1) : "l"(w[i + 1]), "l"(h1), "l"(a1));
            asm("fma.rn.f32x2 %0, %1, %2, %3;" : "=l"(a2) : "l"(w[i + 2]), "l"(h2), "l"(a2));
            asm("fma.rn.f32x2 %0, %1, %2, %3;" : "=l"(a3) : "l"(w[i + 3]), "l"(h3), "l"(a3));
        }
        float x0, y0, x1, y1, x2, y2, x3, y3;
        asm("mov.b64 {%0, %1}, %2;" : "=f"(x0), "=f"(y0) : "l"(a0));
        asm("mov.b64 {%0, %1}, %2;" : "=f"(x1), "=f"(y1) : "l"(a1));
        asm("mov.b64 {%0, %1}, %2;" : "=f"(x2), "=f"(y2) : "l"(a2));
        asm("mov.b64 {%0, %1}, %2;" : "=f"(x3), "=f"(y3) : "l"(a3));
        float v = gcur + ((x0 + y0) + (x1 + y1)) + ((x2 + y2) + (x3 + y3));

        int par = s & 1;
        unsigned vbits = __float_as_uint(v);
        #pragma unroll
        for (int peer = 0; peer < 4; peer++) {
            asm volatile(
                "st.async.shared::cluster.mbarrier::complete_tx::bytes.b32 [%0], %1, [%2];"
                :: "r"(gadr[par][peer]), "r"(vbits), "r"(madr[par][peer]) : "memory");
        }

        float gnext = 0.f;
        if (s + 1 < TT) gnext = gp[(size_t)(t + tstep) * 1024];

        __syncthreads();   // all local hsh reads done before the update writes

        unsigned mb = par ? mloc[1] : mloc[0];
        int phv = par ? ph1 : ph0;
        MBAR_WAIT_PARITY(mb, phv);
        if (par) ph1 ^= 1; else ph0 ^= 1;
        if (tid == 0 && s + 2 < TT) MBAR_EXPECT_TX(mb, 2048);

        float ig = fsigmoid(gb[par][tid]);
        float fg = fsigmoid(gb[par][tid + 128]);
        float gg = ftanh(gb[par][tid + 256]);
        float og = fsigmoid(gb[par][tid + 384]);
        c = fg * c + ig * gg;
        float h = og * ftanh(c);
        hsh[tid] = h;
        if (rank == 0)
            hout[((size_t)b * TT + t) * 256 + d * HH + tid] = h;
        __syncthreads();

        t += tstep;
        gcur = gnext;
    }

    asm volatile("barrier.cluster.arrive.aligned;" ::: "memory");
    asm volatile("barrier.cluster.wait.aligned;" ::: "memory");
}

// ---------------- mean over nodes ----------------
__global__ void agg_kernel(const float* __restrict__ lo, float* __restrict__ agg) {
    int b = blockIdx.x, o = threadIdx.x;
    float s = 0.f;
    const float* lb = lo + (size_t)b * TT * 256 + o;
    #pragma unroll 4
    for (int t = 0; t < TT; t++) s += lb[(size_t)t * 256];
    agg[b * 256 + o] = s * (1.0f / 256.0f);
}

// ---------------- host launcher ----------------
extern "C" void kernel_launch(void* const* d_in, const int* in_sizes, int n_in,
                              void* d_out, int out_size)
{
    const float* x         = (const float*)d_in[0];
    const float* cheb_w    = (const float*)d_in[5];   // [2,256,256] = [512,256] stacked
    const float* cheb_b    = (const float*)d_in[6];
    const float* ln_cheb_g = (const float*)d_in[7];
    const float* ln_cheb_b = (const float*)d_in[8];
    const float* w_ih      = (const float*)d_in[9];   // [2,2,512,256]
    const float* w_hh      = (const float*)d_in[10];  // [2,2,512,128]
    const float* b_ih      = (const float*)d_in[11];  // [2,2,512]
    const float* b_hh      = (const float*)d_in[12];
    const float* ln_out_g  = (const float*)d_in[13];
    const float* ln_out_b  = (const float*)d_in[14];

    float* out = (float*)d_out;
    float* agg = out;                          // [8,256]
    float* tg  = out + BB * 256;               // [8,256,256]
    float* lo  = tg + BB * NN * NN;            // [8,256,256]

    float *S, *ctmp, *cout, *gin, *h1, *h2;
    cudaGetSymbolAddress((void**)&S,    g_S);
    cudaGetSymbolAddress((void**)&ctmp, g_ctmp);
    cudaGetSymbolAddress((void**)&cout, g_cout);
    cudaGetSymbolAddress((void**)&gin,  g_gin);
    cudaGetSymbolAddress((void**)&h1,   g_h1);
    cudaGetSymbolAddress((void**)&h2,   g_h2);

    // colsum + TG constant fill in one launch (8 + 512 blocks)
    colsum_fill_kernel<<<BB + 512, 256>>>(x, S, tg);

    // ChebConv: ctmp = [x | (x+S/256)/2] @ [W0;W1] + cheb_b (pk1 fused into loadA)
    gemm_db<false, true><<<dim3(FF/64, ROWS/64), 256>>>(
        x, S, cheb_w, ctmp, ROWS, FF, 512, cheb_b, nullptr);
    ln256_kernel<<<ROWS, 256>>>(ctmp, ln_cheb_g, ln_cheb_b, cout);

    // Layer 1: both-dir input gates in ONE 128x128-tile GEMM
    gemm128t<<<dim3(1024/128, ROWS/128), 256>>>(
        cout, w_ih, gin, ROWS, 1024, FF, b_ih, b_hh);
    lstm_scan_cluster<<<64, 128>>>(gin, w_hh, h1);

    // Layer 2
    gemm128t<<<dim3(1024/128, ROWS/128), 256>>>(
        h1, w_ih + (size_t)2 * G4 * FF, gin, ROWS, 1024, 2 * HH,
        b_ih + 2 * G4, b_hh + 2 * G4);
    lstm_scan_cluster<<<64, 128>>>(gin, w_hh + (size_t)2 * G4 * HH, h2);

    // Final LN -> lstm_out, then node-mean -> agg
    ln256_kernel<<<ROWS, 256>>>(h2, ln_out_g, ln_out_b, lo);
    agg_kernel<<<BB, 256>>>(lo, agg);
}